// round 2
// baseline (speedup 1.0000x reference)
#include <cuda_runtime.h>
#include <cuda_bf16.h>
#include <cstdint>
#include <math.h>

#define NB 512
#define SEQ 128
#define D 256
#define NREST (NB * (SEQ - 1))   // 65024

#define BM 128
#define BN 128
#define BK 32
#define NKT (D / BK)             // 8 k-tiles
#define SSTRIDE (BK + 8)         // 40 bf16 elems = 80B row stride (conflict-free LDSM)

// ---------------- device scratch (no allocs allowed) ----------------
__device__ __nv_bfloat16 g_anchors[NB * D];
__device__ __nv_bfloat16 g_rest[(size_t)NREST * D];
__device__ float g_tot[NB];
__device__ float g_pos[NB];
__device__ int   g_labels[NB];

__device__ __forceinline__ uint32_t smem_u32(const void* p) {
    return (uint32_t)__cvta_generic_to_shared(p);
}

// ---------------- kernel 0: init accumulators + labels ----------------
// NOTE: labels arrive as int32 (JAX default x64-disabled downcasts int64->int32)
__global__ void init_kernel(const int* __restrict__ lab) {
    int i = threadIdx.x;            // 512 threads
    g_tot[i] = 0.0f;
    g_pos[i] = 0.0f;
    g_labels[i] = lab[i];
}

// ---------------- kernel 1: L2-normalize rows, write bf16 ----------------
// one warp per (b,l) row; lane handles 8 contiguous elements
__global__ void normalize_kernel(const float* __restrict__ inp) {
    int row  = blockIdx.x * 8 + (threadIdx.x >> 5);
    int lane = threadIdx.x & 31;
    const float4* p = reinterpret_cast<const float4*>(inp + (size_t)row * D) + lane * 2;
    float4 a = p[0];
    float4 b = p[1];
    float ss = a.x*a.x + a.y*a.y + a.z*a.z + a.w*a.w
             + b.x*b.x + b.y*b.y + b.z*b.z + b.w*b.w;
    #pragma unroll
    for (int o = 16; o > 0; o >>= 1) ss += __shfl_xor_sync(0xffffffffu, ss, o);
    float scale = 1.0f / fmaxf(sqrtf(ss), 1e-12f);

    int bidx = row >> 7;
    int l    = row & 127;
    __nv_bfloat16* dst = (l == 0)
        ? (g_anchors + (size_t)bidx * D)
        : (g_rest + (size_t)(bidx * (SEQ - 1) + (l - 1)) * D);

    __nv_bfloat162 v0 = __floats2bfloat162_rn(a.x * scale, a.y * scale);
    __nv_bfloat162 v1 = __floats2bfloat162_rn(a.z * scale, a.w * scale);
    __nv_bfloat162 v2 = __floats2bfloat162_rn(b.x * scale, b.y * scale);
    __nv_bfloat162 v3 = __floats2bfloat162_rn(b.z * scale, b.w * scale);
    uint4 u;
    u.x = *reinterpret_cast<uint32_t*>(&v0);
    u.y = *reinterpret_cast<uint32_t*>(&v1);
    u.z = *reinterpret_cast<uint32_t*>(&v2);
    u.w = *reinterpret_cast<uint32_t*>(&v3);
    *reinterpret_cast<uint4*>(dst + lane * 8) = u;
}

// ---------------- kernel 2: fused GEMM + exp + masked row-sum ----------------
// scores(i, (j,k)) = anchors[i] . rest[(j,k)];   tot[i] += exp(s);  pos[i] += same(i,j)*exp(s)
__global__ __launch_bounds__(256, 2) void score_kernel() {
    __shared__ __align__(16) __nv_bfloat16 sA[2][BM][SSTRIDE];
    __shared__ __align__(16) __nv_bfloat16 sB[2][BN][SSTRIDE];
    __shared__ float sTot[BM];
    __shared__ float sPos[BM];
    __shared__ int   sRowLab[BM];
    __shared__ int   sColLab[BN];

    int tid  = threadIdx.x;
    int lane = tid & 31;
    int warp = tid >> 5;
    int wm = (warp & 3) * 32;   // warp m-offset (4 warps along M)
    int wn = (warp >> 2) * 64;  // warp n-offset (2 warps along N)
    int bm = blockIdx.x * BM;
    int bn = blockIdx.y * BN;

    if (tid < BM) {
        sTot[tid] = 0.0f;
        sPos[tid] = 0.0f;
        sRowLab[tid] = g_labels[bm + tid];
        sColLab[tid] = g_labels[(bn + tid) / (SEQ - 1)];
    }

    // global load pointers: each thread owns two 16B chunks per operand per k-tile
    const __nv_bfloat16* gA = g_anchors + (size_t)(bm + (tid >> 2)) * D + (tid & 3) * 8;
    const __nv_bfloat16* gB = g_rest    + (size_t)(bn + (tid >> 2)) * D + (tid & 3) * 8;
    int sr = tid >> 2;
    int sc = (tid & 3) * 8;

    float acc[2][8][4];
    #pragma unroll
    for (int mf = 0; mf < 2; mf++)
        #pragma unroll
        for (int nf = 0; nf < 8; nf++)
            #pragma unroll
            for (int r = 0; r < 4; r++) acc[mf][nf][r] = 0.0f;

    // prefetch k-tile 0 -> smem buf 0
    uint4 pa0 = *reinterpret_cast<const uint4*>(gA);
    uint4 pa1 = *reinterpret_cast<const uint4*>(gA + 64 * D);
    uint4 pb0 = *reinterpret_cast<const uint4*>(gB);
    uint4 pb1 = *reinterpret_cast<const uint4*>(gB + 64 * D);
    *reinterpret_cast<uint4*>(&sA[0][sr][sc])      = pa0;
    *reinterpret_cast<uint4*>(&sA[0][sr + 64][sc]) = pa1;
    *reinterpret_cast<uint4*>(&sB[0][sr][sc])      = pb0;
    *reinterpret_cast<uint4*>(&sB[0][sr + 64][sc]) = pb1;
    __syncthreads();

    #pragma unroll
    for (int kt = 0; kt < NKT; kt++) {
        if (kt + 1 < NKT) {
            int ko = (kt + 1) * BK;
            pa0 = *reinterpret_cast<const uint4*>(gA + ko);
            pa1 = *reinterpret_cast<const uint4*>(gA + 64 * D + ko);
            pb0 = *reinterpret_cast<const uint4*>(gB + ko);
            pb1 = *reinterpret_cast<const uint4*>(gB + 64 * D + ko);
        }
        int buf = kt & 1;
        #pragma unroll
        for (int ks = 0; ks < 2; ks++) {   // two k16 steps per BK=32
            uint32_t afr[2][4];
            #pragma unroll
            for (int mf = 0; mf < 2; mf++) {
                uint32_t addr = smem_u32(&sA[buf][wm + mf * 16 + (lane & 15)]
                                            [ks * 16 + (lane >> 4) * 8]);
                asm volatile("ldmatrix.sync.aligned.m8n8.x4.shared.b16 {%0,%1,%2,%3}, [%4];"
                             : "=r"(afr[mf][0]), "=r"(afr[mf][1]),
                               "=r"(afr[mf][2]), "=r"(afr[mf][3])
                             : "r"(addr));
            }
            uint32_t bfr[8][2];
            #pragma unroll
            for (int np = 0; np < 4; np++) {
                uint32_t addr = smem_u32(&sB[buf][wn + np * 16 + (lane >> 4) * 8 + (lane & 7)]
                                            [ks * 16 + ((lane >> 3) & 1) * 8]);
                asm volatile("ldmatrix.sync.aligned.m8n8.x4.shared.b16 {%0,%1,%2,%3}, [%4];"
                             : "=r"(bfr[2 * np][0]), "=r"(bfr[2 * np][1]),
                               "=r"(bfr[2 * np + 1][0]), "=r"(bfr[2 * np + 1][1])
                             : "r"(addr));
            }
            #pragma unroll
            for (int mf = 0; mf < 2; mf++)
                #pragma unroll
                for (int nf = 0; nf < 8; nf++)
                    asm volatile(
                        "mma.sync.aligned.m16n8k16.row.col.f32.bf16.bf16.f32 "
                        "{%0,%1,%2,%3}, {%4,%5,%6,%7}, {%8,%9}, {%0,%1,%2,%3};"
                        : "+f"(acc[mf][nf][0]), "+f"(acc[mf][nf][1]),
                          "+f"(acc[mf][nf][2]), "+f"(acc[mf][nf][3])
                        : "r"(afr[mf][0]), "r"(afr[mf][1]), "r"(afr[mf][2]), "r"(afr[mf][3]),
                          "r"(bfr[nf][0]), "r"(bfr[nf][1]));
        }
        if (kt + 1 < NKT) {
            int nb = (kt + 1) & 1;
            *reinterpret_cast<uint4*>(&sA[nb][sr][sc])      = pa0;
            *reinterpret_cast<uint4*>(&sA[nb][sr + 64][sc]) = pa1;
            *reinterpret_cast<uint4*>(&sB[nb][sr][sc])      = pb0;
            *reinterpret_cast<uint4*>(&sB[nb][sr + 64][sc]) = pb1;
            __syncthreads();
        }
    }

    // epilogue: exp + masked row-sums
    int qr = lane >> 2;
    int qc = (lane & 3) * 2;
    #pragma unroll
    for (int mf = 0; mf < 2; mf++) {
        #pragma unroll
        for (int h = 0; h < 2; h++) {
            int lrow = wm + mf * 16 + h * 8 + qr;
            int mylab = sRowLab[lrow];
            float ts = 0.0f, ps = 0.0f;
            #pragma unroll
            for (int nf = 0; nf < 8; nf++) {
                int c = wn + nf * 8 + qc;
                float e0 = __expf(acc[mf][nf][h * 2 + 0]);
                float e1 = __expf(acc[mf][nf][h * 2 + 1]);
                ts += e0 + e1;
                ps += (sColLab[c]     == mylab) ? e0 : 0.0f;
                ps += (sColLab[c + 1] == mylab) ? e1 : 0.0f;
            }
            ts += __shfl_xor_sync(0xffffffffu, ts, 1);
            ts += __shfl_xor_sync(0xffffffffu, ts, 2);
            ps += __shfl_xor_sync(0xffffffffu, ps, 1);
            ps += __shfl_xor_sync(0xffffffffu, ps, 2);
            if ((lane & 3) == 0) {
                atomicAdd(&sTot[lrow], ts);
                atomicAdd(&sPos[lrow], ps);
            }
        }
    }
    __syncthreads();
    if (tid < BM) {
        atomicAdd(&g_tot[bm + tid], sTot[tid]);
        atomicAdd(&g_pos[bm + tid], sPos[tid]);
    }
}

// ---------------- kernel 3: loss = mean(log tot - log pos) ----------------
__global__ void finalize_kernel(float* __restrict__ out) {
    __shared__ float red[512];
    int i = threadIdx.x;
    red[i] = logf(g_tot[i]) - logf(g_pos[i]);
    __syncthreads();
    #pragma unroll
    for (int s = 256; s > 0; s >>= 1) {
        if (i < s) red[i] += red[i + s];
        __syncthreads();
    }
    if (i == 0) out[0] = red[0] * (1.0f / 512.0f);
}

// ---------------- launch ----------------
extern "C" void kernel_launch(void* const* d_in, const int* in_sizes, int n_in,
                              void* d_out, int out_size) {
    const float* inp = (const float*)d_in[0];
    const int*   lab = (const int*)d_in[1];
    float*       out = (float*)d_out;

    init_kernel<<<1, 512>>>(lab);
    normalize_kernel<<<(NB * SEQ) / 8, 256>>>(inp);
    score_kernel<<<dim3(NB / BM, NREST / BN), 256>>>();
    finalize_kernel<<<1, 512>>>(out);
}

// round 4
// speedup vs baseline: 1.1046x; 1.1046x over previous
#include <cuda_runtime.h>
#include <cuda_bf16.h>
#include <cstdint>
#include <math.h>

#define NB 512
#define SEQ 128
#define D 256
#define NREST 65024            // NB*(SEQ-1)

#define BM 128
#define BN 128
#define BK 32
#define NKT (D / BK)           // 8
#define STAGES 4
#define SSTRIDE 40             // bf16 elems; 80B row stride, conflict-free LDSM
#define STAGE_BYTES (BM * SSTRIDE * 2)       // 10240 per operand per stage
#define GRIDX 4                // anchor groups (NB/BM)
#define GRIDY (NREST / BN)     // 508
#define TOTAL_BLOCKS (GRIDX * GRIDY)

// dynamic smem layout (bytes)
#define SM_A 0
#define SM_B (STAGES * STAGE_BYTES)                  // 40960
#define SM_MISC (2 * STAGES * STAGE_BYTES)           // 81920
#define SM_TOTAL (SM_MISC + 2 * BM * 4 + 2 * BM * 4 + 64)

// ---------------- device scratch ----------------
__device__ __nv_bfloat16 g_anchors[NB * D];
__device__ __nv_bfloat16 g_rest[(size_t)NREST * D];
__device__ int   g_labels[NB];
__device__ int   g_collab[NREST];
__device__ float g_tot[NB];
__device__ float g_pos[NB];
__device__ unsigned g_done;

__device__ __forceinline__ uint32_t smem_u32(const void* p) {
    return (uint32_t)__cvta_generic_to_shared(p);
}
__device__ __forceinline__ void cp_async16(uint32_t dst, const void* src) {
    asm volatile("cp.async.cg.shared.global [%0], [%1], 16;" :: "r"(dst), "l"(src) : "memory");
}
__device__ __forceinline__ void cp_commit() {
    asm volatile("cp.async.commit_group;" ::: "memory");
}
__device__ __forceinline__ void cp_wait2() {
    asm volatile("cp.async.wait_group 2;" ::: "memory");
}

// ---------------- kernel 1: normalize + init ----------------
__global__ void normalize_kernel(const float* __restrict__ inp, const int* __restrict__ lab) {
    int gtid = blockIdx.x * 256 + threadIdx.x;
    if (gtid < NREST) g_collab[gtid] = lab[gtid / (SEQ - 1)];
    if (gtid < NB) { g_tot[gtid] = 0.0f; g_pos[gtid] = 0.0f; g_labels[gtid] = lab[gtid]; }
    if (gtid == 0) g_done = 0u;

    int row  = blockIdx.x * 8 + (threadIdx.x >> 5);
    int lane = threadIdx.x & 31;
    const float4* p = reinterpret_cast<const float4*>(inp + (size_t)row * D) + lane * 2;
    float4 a = p[0];
    float4 b = p[1];
    float ss = a.x*a.x + a.y*a.y + a.z*a.z + a.w*a.w
             + b.x*b.x + b.y*b.y + b.z*b.z + b.w*b.w;
    #pragma unroll
    for (int o = 16; o > 0; o >>= 1) ss += __shfl_xor_sync(0xffffffffu, ss, o);
    float scale = 1.0f / fmaxf(sqrtf(ss), 1e-12f);

    int bidx = row >> 7;
    int l    = row & 127;
    __nv_bfloat16* dst = (l == 0)
        ? (g_anchors + (size_t)bidx * D)
        : (g_rest + (size_t)(bidx * (SEQ - 1) + (l - 1)) * D);

    __nv_bfloat162 v0 = __floats2bfloat162_rn(a.x * scale, a.y * scale);
    __nv_bfloat162 v1 = __floats2bfloat162_rn(a.z * scale, a.w * scale);
    __nv_bfloat162 v2 = __floats2bfloat162_rn(b.x * scale, b.y * scale);
    __nv_bfloat162 v3 = __floats2bfloat162_rn(b.z * scale, b.w * scale);
    uint4 u;
    u.x = *reinterpret_cast<uint32_t*>(&v0);
    u.y = *reinterpret_cast<uint32_t*>(&v1);
    u.z = *reinterpret_cast<uint32_t*>(&v2);
    u.w = *reinterpret_cast<uint32_t*>(&v3);
    *reinterpret_cast<uint4*>(dst + lane * 8) = u;
}

// ---------------- kernel 2: fused GEMM + exp + row-sum + final reduce ----------------
__global__ void __launch_bounds__(256, 2) score_kernel(float* __restrict__ out) {
    extern __shared__ __align__(16) char S[];

    float* sTot    = reinterpret_cast<float*>(S + SM_MISC);
    float* sPos    = sTot + BM;
    int*   sRowLab = reinterpret_cast<int*>(sPos + BM);
    int*   sColLab = sRowLab + BM;
    int*   sFlag   = sColLab + BN;

    int tid  = threadIdx.x;
    int lane = tid & 31;
    int warp = tid >> 5;
    int wm = (warp & 3) * 32;
    int wn = (warp >> 2) * 64;
    int bm = blockIdx.x * BM;
    int bn = blockIdx.y * BN;

    if (tid < BM) {
        sTot[tid] = 0.0f;
        sPos[tid] = 0.0f;
        sRowLab[tid] = g_labels[bm + tid];
        sColLab[tid] = g_collab[bn + tid];
    }

    // per-thread global/smem addressing: 2 rows per operand, one 16B chunk per row
    const __nv_bfloat16* gA = g_anchors + (size_t)(bm + (tid >> 2)) * D + (tid & 3) * 8;
    const __nv_bfloat16* gB = g_rest    + (size_t)(bn + (tid >> 2)) * D + (tid & 3) * 8;
    int sr = tid >> 2;
    int sc = (tid & 3) * 8;
    uint32_t smA = smem_u32(S + SM_A) + (sr * SSTRIDE + sc) * 2;
    uint32_t smB = smem_u32(S + SM_B) + (sr * SSTRIDE + sc) * 2;
    const uint32_t rowHalf = 64 * SSTRIDE * 2;

    // prologue: stages 0,1 (k-tiles 0,1)
    #pragma unroll
    for (int s = 0; s < 2; s++) {
        int ko = s * BK;
        cp_async16(smA + s * STAGE_BYTES,           gA + ko);
        cp_async16(smA + s * STAGE_BYTES + rowHalf, gA + 64 * D + ko);
        cp_async16(smB + s * STAGE_BYTES,           gB + ko);
        cp_async16(smB + s * STAGE_BYTES + rowHalf, gB + 64 * D + ko);
        cp_commit();
    }

    float acc[2][8][4];
    #pragma unroll
    for (int mf = 0; mf < 2; mf++)
        #pragma unroll
        for (int nf = 0; nf < 8; nf++)
            #pragma unroll
            for (int r = 0; r < 4; r++) acc[mf][nf][r] = 0.0f;

    const __nv_bfloat16* sAp = reinterpret_cast<const __nv_bfloat16*>(S + SM_A);
    const __nv_bfloat16* sBp = reinterpret_cast<const __nv_bfloat16*>(S + SM_B);

    #pragma unroll
    for (int kt = 0; kt < NKT; kt++) {
        if (kt + 2 < NKT) {
            int st = (kt + 2) & 3;
            int ko = (kt + 2) * BK;
            cp_async16(smA + st * STAGE_BYTES,           gA + ko);
            cp_async16(smA + st * STAGE_BYTES + rowHalf, gA + 64 * D + ko);
            cp_async16(smB + st * STAGE_BYTES,           gB + ko);
            cp_async16(smB + st * STAGE_BYTES + rowHalf, gB + 64 * D + ko);
        }
        cp_commit();
        cp_wait2();
        __syncthreads();

        const __nv_bfloat16* aBuf = sAp + (kt & 3) * (STAGE_BYTES / 2);
        const __nv_bfloat16* bBuf = sBp + (kt & 3) * (STAGE_BYTES / 2);

        #pragma unroll
        for (int ks = 0; ks < 2; ks++) {
            uint32_t afr[2][4];
            #pragma unroll
            for (int mf = 0; mf < 2; mf++) {
                uint32_t addr = smem_u32(aBuf + (wm + mf * 16 + (lane & 15)) * SSTRIDE
                                              + ks * 16 + (lane >> 4) * 8);
                asm volatile("ldmatrix.sync.aligned.m8n8.x4.shared.b16 {%0,%1,%2,%3}, [%4];"
                             : "=r"(afr[mf][0]), "=r"(afr[mf][1]),
                               "=r"(afr[mf][2]), "=r"(afr[mf][3])
                             : "r"(addr));
            }
            uint32_t bfr[8][2];
            #pragma unroll
            for (int np = 0; np < 4; np++) {
                uint32_t addr = smem_u32(bBuf + (wn + np * 16 + (lane >> 4) * 8 + (lane & 7)) * SSTRIDE
                                              + ks * 16 + ((lane >> 3) & 1) * 8);
                asm volatile("ldmatrix.sync.aligned.m8n8.x4.shared.b16 {%0,%1,%2,%3}, [%4];"
                             : "=r"(bfr[2 * np][0]), "=r"(bfr[2 * np][1]),
                               "=r"(bfr[2 * np + 1][0]), "=r"(bfr[2 * np + 1][1])
                             : "r"(addr));
            }
            #pragma unroll
            for (int mf = 0; mf < 2; mf++)
                #pragma unroll
                for (int nf = 0; nf < 8; nf++)
                    asm volatile(
                        "mma.sync.aligned.m16n8k16.row.col.f32.bf16.bf16.f32 "
                        "{%0,%1,%2,%3}, {%4,%5,%6,%7}, {%8,%9}, {%0,%1,%2,%3};"
                        : "+f"(acc[mf][nf][0]), "+f"(acc[mf][nf][1]),
                          "+f"(acc[mf][nf][2]), "+f"(acc[mf][nf][3])
                        : "r"(afr[mf][0]), "r"(afr[mf][1]), "r"(afr[mf][2]), "r"(afr[mf][3]),
                          "r"(bfr[nf][0]), "r"(bfr[nf][1]));
        }
    }

    // epilogue: exp + masked row-sums
    int qr = lane >> 2;
    int qc = (lane & 3) * 2;
    #pragma unroll
    for (int mf = 0; mf < 2; mf++) {
        #pragma unroll
        for (int h = 0; h < 2; h++) {
            int lrow = wm + mf * 16 + h * 8 + qr;
            int mylab = sRowLab[lrow];
            float ts = 0.0f, ps = 0.0f;
            #pragma unroll
            for (int nf = 0; nf < 8; nf++) {
                int c = wn + nf * 8 + qc;
                float e0 = __expf(acc[mf][nf][h * 2 + 0]);
                float e1 = __expf(acc[mf][nf][h * 2 + 1]);
                ts += e0 + e1;
                ps += (sColLab[c]     == mylab) ? e0 : 0.0f;
                ps += (sColLab[c + 1] == mylab) ? e1 : 0.0f;
            }
            ts += __shfl_xor_sync(0xffffffffu, ts, 1);
            ts += __shfl_xor_sync(0xffffffffu, ts, 2);
            ps += __shfl_xor_sync(0xffffffffu, ps, 1);
            ps += __shfl_xor_sync(0xffffffffu, ps, 2);
            if ((lane & 3) == 0) {
                atomicAdd(&sTot[lrow], ts);
                atomicAdd(&sPos[lrow], ps);
            }
        }
    }
    __syncthreads();
    if (tid < BM) {
        atomicAdd(&g_tot[bm + tid], sTot[tid]);
        atomicAdd(&g_pos[bm + tid], sPos[tid]);
    }

    // ---- fused finalize: last CTA computes the loss ----
    __threadfence();
    __syncthreads();
    if (tid == 0) {
        unsigned v = atomicAdd(&g_done, 1u);
        sFlag[0] = (v == TOTAL_BLOCKS - 1) ? 1 : 0;
    }
    __syncthreads();
    if (sFlag[0]) {
        __threadfence();
        float v = (logf(g_tot[tid]) - logf(g_pos[tid]))
                + (logf(g_tot[tid + 256]) - logf(g_pos[tid + 256]));
        #pragma unroll
        for (int o = 16; o > 0; o >>= 1) v += __shfl_xor_sync(0xffffffffu, v, o);
        float* red = sTot;   // reuse
        if (lane == 0) red[warp] = v;
        __syncthreads();
        if (tid == 0) {
            float s = 0.0f;
            #pragma unroll
            for (int w = 0; w < 8; w++) s += red[w];
            out[0] = s * (1.0f / 512.0f);
        }
    }
}

// ---------------- launch ----------------
extern "C" void kernel_launch(void* const* d_in, const int* in_sizes, int n_in,
                              void* d_out, int out_size) {
    const float* inp = (const float*)d_in[0];
    const int*   lab = (const int*)d_in[1];
    float*       out = (float*)d_out;

    cudaFuncSetAttribute(score_kernel, cudaFuncAttributeMaxDynamicSharedMemorySize, SM_TOTAL);

    normalize_kernel<<<(NB * SEQ) / 8, 256>>>(inp, lab);
    score_kernel<<<dim3(GRIDX, GRIDY), 256, SM_TOTAL>>>(out);
}

// round 5
// speedup vs baseline: 1.1333x; 1.0260x over previous
#include <cuda_runtime.h>
#include <cuda_bf16.h>
#include <cstdint>
#include <math.h>

#define NB 512
#define SEQ 128
#define D 256
#define NREST 65024            // NB*(SEQ-1)

#define BM 128
#define BN 128
#define BK 64
#define NKT (D / BK)           // 4
#define SSTRIDE 72             // bf16 elems; 144B row stride, conflict-free LDSM
#define STAGE_BYTES (BM * SSTRIDE * 2)       // 18432 per operand per stage
#define GRIDX 4                // anchor groups (NB/BM)
#define GRIDY (NREST / BN)     // 508
#define TOTAL_BLOCKS (GRIDX * GRIDY)

// dynamic smem layout (bytes): 3 A stages, 3 B stages, misc
#define SM_A 0
#define SM_B (3 * STAGE_BYTES)               // 55296
#define SM_MISC (6 * STAGE_BYTES)            // 110592
#define SM_TOTAL (SM_MISC + 4 * BM * 4 + 64)

// ---------------- device scratch ----------------
__device__ __nv_bfloat16 g_anchors[NB * D];
__device__ __nv_bfloat16 g_rest[(size_t)NREST * D];
__device__ int   g_labels[NB];
__device__ int   g_collab[NREST];
__device__ float g_tot[NB];
__device__ float g_pos[NB];
__device__ unsigned g_done;

__device__ __forceinline__ uint32_t smem_u32(const void* p) {
    return (uint32_t)__cvta_generic_to_shared(p);
}
__device__ __forceinline__ void cp_async16(uint32_t dst, const void* src) {
    asm volatile("cp.async.cg.shared.global [%0], [%1], 16;" :: "r"(dst), "l"(src) : "memory");
}
__device__ __forceinline__ void cp_commit() {
    asm volatile("cp.async.commit_group;" ::: "memory");
}
template <int N>
__device__ __forceinline__ void cp_wait() {
    asm volatile("cp.async.wait_group %0;" :: "n"(N) : "memory");
}

// ---------------- kernel 1: normalize + init ----------------
__global__ void normalize_kernel(const float* __restrict__ inp, const int* __restrict__ lab) {
    int gtid = blockIdx.x * 256 + threadIdx.x;
    if (gtid < NREST) g_collab[gtid] = lab[gtid / (SEQ - 1)];
    if (gtid < NB) { g_tot[gtid] = 0.0f; g_pos[gtid] = 0.0f; g_labels[gtid] = lab[gtid]; }
    if (gtid == 0) g_done = 0u;

    int row  = blockIdx.x * 8 + (threadIdx.x >> 5);
    int lane = threadIdx.x & 31;
    const float4* p = reinterpret_cast<const float4*>(inp + (size_t)row * D) + lane * 2;
    float4 a = p[0];
    float4 b = p[1];
    float ss = a.x*a.x + a.y*a.y + a.z*a.z + a.w*a.w
             + b.x*b.x + b.y*b.y + b.z*b.z + b.w*b.w;
    #pragma unroll
    for (int o = 16; o > 0; o >>= 1) ss += __shfl_xor_sync(0xffffffffu, ss, o);
    float scale = 1.0f / fmaxf(sqrtf(ss), 1e-12f);

    int bidx = row >> 7;
    int l    = row & 127;
    __nv_bfloat16* dst = (l == 0)
        ? (g_anchors + (size_t)bidx * D)
        : (g_rest + (size_t)(bidx * (SEQ - 1) + (l - 1)) * D);

    __nv_bfloat162 v0 = __floats2bfloat162_rn(a.x * scale, a.y * scale);
    __nv_bfloat162 v1 = __floats2bfloat162_rn(a.z * scale, a.w * scale);
    __nv_bfloat162 v2 = __floats2bfloat162_rn(b.x * scale, b.y * scale);
    __nv_bfloat162 v3 = __floats2bfloat162_rn(b.z * scale, b.w * scale);
    uint4 u;
    u.x = *reinterpret_cast<uint32_t*>(&v0);
    u.y = *reinterpret_cast<uint32_t*>(&v1);
    u.z = *reinterpret_cast<uint32_t*>(&v2);
    u.w = *reinterpret_cast<uint32_t*>(&v3);
    *reinterpret_cast<uint4*>(dst + lane * 8) = u;
}

// ---------------- kernel 2: fused GEMM + exp + row-sum + final reduce ----------------
__global__ void __launch_bounds__(256, 2) score_kernel(float* __restrict__ out) {
    extern __shared__ __align__(16) char S[];

    float* sTot    = reinterpret_cast<float*>(S + SM_MISC);
    float* sPos    = sTot + BM;
    int*   sRowLab = reinterpret_cast<int*>(sPos + BM);
    int*   sColLab = sRowLab + BM;
    int*   sFlag   = sColLab + BN;

    int tid  = threadIdx.x;
    int lane = tid & 31;
    int warp = tid >> 5;
    int wm = (warp & 3) * 32;
    int wn = (warp >> 2) * 64;
    int bm = blockIdx.x * BM;
    int bn = blockIdx.y * BN;

    if (tid < BM) {
        sTot[tid] = 0.0f;
        sPos[tid] = 0.0f;
        sRowLab[tid] = g_labels[bm + tid];
        sColLab[tid] = g_collab[bn + tid];
    }

    // loader mapping: each thread owns 4 (row, chunk) pairs per operand per tile
    // idx = tid + i*256 ; row = idx>>3 ; chunk = idx&7  (chunk = 16B = 8 bf16)
    const __nv_bfloat16* gA = g_anchors + (size_t)bm * D;
    const __nv_bfloat16* gB = g_rest    + (size_t)bn * D;
    uint32_t smA = smem_u32(S + SM_A);
    uint32_t smB = smem_u32(S + SM_B);

    #define ISSUE_TILE(kt_, st_)                                                   \
        do {                                                                       \
            int _ko = (kt_) * BK;                                                  \
            _Pragma("unroll")                                                      \
            for (int i = 0; i < 4; i++) {                                          \
                int idx = tid + i * 256;                                           \
                int r = idx >> 3, c = idx & 7;                                     \
                uint32_t so = (st_) * STAGE_BYTES + (r * SSTRIDE + c * 8) * 2;     \
                cp_async16(smA + so, gA + (size_t)r * D + _ko + c * 8);            \
                cp_async16(smB + so, gB + (size_t)r * D + _ko + c * 8);            \
            }                                                                      \
            cp_commit();                                                           \
        } while (0)

    // prologue: tiles 0,1,2 -> stages 0,1,2
    ISSUE_TILE(0, 0);
    ISSUE_TILE(1, 1);
    ISSUE_TILE(2, 2);

    float acc[2][8][4];
    #pragma unroll
    for (int mf = 0; mf < 2; mf++)
        #pragma unroll
        for (int nf = 0; nf < 8; nf++)
            #pragma unroll
            for (int r = 0; r < 4; r++) acc[mf][nf][r] = 0.0f;

    const __nv_bfloat16* sAp = reinterpret_cast<const __nv_bfloat16*>(S + SM_A);
    const __nv_bfloat16* sBp = reinterpret_cast<const __nv_bfloat16*>(S + SM_B);

    #pragma unroll
    for (int kt = 0; kt < NKT; kt++) {
        // tile kt is in group kt; groups retire in order
        if (kt == 0) cp_wait<2>();
        else if (kt == 1) cp_wait<2>();
        else if (kt == 2) cp_wait<1>();
        else cp_wait<0>();
        __syncthreads();

        const __nv_bfloat16* aBuf = sAp + (kt % 3) * (STAGE_BYTES / 2);
        const __nv_bfloat16* bBuf = sBp + (kt % 3) * (STAGE_BYTES / 2);

        #pragma unroll
        for (int ks = 0; ks < 4; ks++) {   // four k16 steps per BK=64
            uint32_t afr[2][4];
            #pragma unroll
            for (int mf = 0; mf < 2; mf++) {
                uint32_t addr = smem_u32(aBuf + (wm + mf * 16 + (lane & 15)) * SSTRIDE
                                              + ks * 16 + (lane >> 4) * 8);
                asm volatile("ldmatrix.sync.aligned.m8n8.x4.shared.b16 {%0,%1,%2,%3}, [%4];"
                             : "=r"(afr[mf][0]), "=r"(afr[mf][1]),
                               "=r"(afr[mf][2]), "=r"(afr[mf][3])
                             : "r"(addr));
            }
            uint32_t bfr[8][2];
            #pragma unroll
            for (int np = 0; np < 4; np++) {
                uint32_t addr = smem_u32(bBuf + (wn + np * 16 + (lane >> 4) * 8 + (lane & 7)) * SSTRIDE
                                              + ks * 16 + ((lane >> 3) & 1) * 8);
                asm volatile("ldmatrix.sync.aligned.m8n8.x4.shared.b16 {%0,%1,%2,%3}, [%4];"
                             : "=r"(bfr[2 * np][0]), "=r"(bfr[2 * np][1]),
                               "=r"(bfr[2 * np + 1][0]), "=r"(bfr[2 * np + 1][1])
                             : "r"(addr));
            }
            #pragma unroll
            for (int mf = 0; mf < 2; mf++)
                #pragma unroll
                for (int nf = 0; nf < 8; nf++)
                    asm volatile(
                        "mma.sync.aligned.m16n8k16.row.col.f32.bf16.bf16.f32 "
                        "{%0,%1,%2,%3}, {%4,%5,%6,%7}, {%8,%9}, {%0,%1,%2,%3};"
                        : "+f"(acc[mf][nf][0]), "+f"(acc[mf][nf][1]),
                          "+f"(acc[mf][nf][2]), "+f"(acc[mf][nf][3])
                        : "r"(afr[mf][0]), "r"(afr[mf][1]), "r"(afr[mf][2]), "r"(afr[mf][3]),
                          "r"(bfr[nf][0]), "r"(bfr[nf][1]));
        }

        if (kt == 0) {
            // stage 0 fully consumed by all warps -> safe to overwrite with tile 3
            __syncthreads();
            ISSUE_TILE(3, 0);
        }
    }

    // epilogue: exp + masked row-sums
    int qr = lane >> 2;
    int qc = (lane & 3) * 2;
    #pragma unroll
    for (int mf = 0; mf < 2; mf++) {
        #pragma unroll
        for (int h = 0; h < 2; h++) {
            int lrow = wm + mf * 16 + h * 8 + qr;
            int mylab = sRowLab[lrow];
            float ts = 0.0f, ps = 0.0f;
            #pragma unroll
            for (int nf = 0; nf < 8; nf++) {
                int c = wn + nf * 8 + qc;
                float e0 = __expf(acc[mf][nf][h * 2 + 0]);
                float e1 = __expf(acc[mf][nf][h * 2 + 1]);
                ts += e0 + e1;
                ps += (sColLab[c]     == mylab) ? e0 : 0.0f;
                ps += (sColLab[c + 1] == mylab) ? e1 : 0.0f;
            }
            ts += __shfl_xor_sync(0xffffffffu, ts, 1);
            ts += __shfl_xor_sync(0xffffffffu, ts, 2);
            ps += __shfl_xor_sync(0xffffffffu, ps, 1);
            ps += __shfl_xor_sync(0xffffffffu, ps, 2);
            if ((lane & 3) == 0) {
                atomicAdd(&sTot[lrow], ts);
                atomicAdd(&sPos[lrow], ps);
            }
        }
    }
    __syncthreads();
    if (tid < BM) {
        atomicAdd(&g_tot[bm + tid], sTot[tid]);
        atomicAdd(&g_pos[bm + tid], sPos[tid]);
    }

    // ---- fused finalize: last CTA computes the loss ----
    __threadfence();
    __syncthreads();
    if (tid == 0) {
        unsigned v = atomicAdd(&g_done, 1u);
        sFlag[0] = (v == TOTAL_BLOCKS - 1) ? 1 : 0;
    }
    __syncthreads();
    if (sFlag[0]) {
        __threadfence();
        float v = (logf(g_tot[tid]) - logf(g_pos[tid]))
                + (logf(g_tot[tid + 256]) - logf(g_pos[tid + 256]));
        #pragma unroll
        for (int o = 16; o > 0; o >>= 1) v += __shfl_xor_sync(0xffffffffu, v, o);
        float* red = sTot;   // reuse
        if (lane == 0) red[warp] = v;
        __syncthreads();
        if (tid == 0) {
            float s = 0.0f;
            #pragma unroll
            for (int w = 0; w < 8; w++) s += red[w];
            out[0] = s * (1.0f / 512.0f);
        }
    }
}

// ---------------- launch ----------------
extern "C" void kernel_launch(void* const* d_in, const int* in_sizes, int n_in,
                              void* d_out, int out_size) {
    const float* inp = (const float*)d_in[0];
    const int*   lab = (const int*)d_in[1];
    float*       out = (float*)d_out;

    cudaFuncSetAttribute(score_kernel, cudaFuncAttributeMaxDynamicSharedMemorySize, SM_TOTAL);

    normalize_kernel<<<(NB * SEQ) / 8, 256>>>(inp, lab);
    score_kernel<<<dim3(GRIDX, GRIDY), 256, SM_TOTAL>>>(out);
}